// round 9
// baseline (speedup 1.0000x reference)
#include <cuda_runtime.h>
#include <math.h>

#define BB 16
#define SS 1024
#define NB 64
#define NSTEP 16   // 1024/64

// ---- static device scratch (allocation-free) ----
static __device__ float g_M [(size_t)BB * SS * SS];   // 64 MB: padded minors -> inverses
static __device__ float g_S [(size_t)BB * NB * SS];   // 4 MB: stashed old row stripe
static __device__ float g_P [(size_t)BB * NB * NB];   // 256 KB: current pivot inverse P^-1
static __device__ float g_diag[BB * SS];              // diag(Minv)
static __device__ unsigned long long g_maxkey;        // (sortable-key<<32)|argmax

__device__ __forceinline__ unsigned int enc_f(float v) {
    unsigned int u = __float_as_uint(v);
    return (u & 0x80000000u) ? ~u : (u | 0x80000000u);
}
__device__ __forceinline__ float dec_f(unsigned int k) {
    unsigned int u = (k & 0x80000000u) ? (k ^ 0x80000000u) : ~k;
    return __uint_as_float(u);
}
__device__ __forceinline__ float get_m() { return dec_f((unsigned int)(g_maxkey >> 32)); }

// ---- packed f32x2 helpers (base Blackwell ISA) ----
__device__ __forceinline__ unsigned long long dup2(float x) {
    unsigned long long r;
    asm("mov.b64 %0, {%1, %1};" : "=l"(r) : "f"(x));
    return r;
}
__device__ __forceinline__ void ffma2(unsigned long long& d, unsigned long long a,
                                      unsigned long long b) {
    asm("fma.rn.f32x2 %0, %1, %2, %0;" : "+l"(d) : "l"(a), "l"(b));
}

// ---- register Gauss-Jordan inversion of a 64x64 block (8 warps x 8 rows x 2 cols/lane) ----
__device__ __forceinline__ void gj64(float pr[8][2], float (*rowbuf)[64], int w, int l) {
    for (int pw = 0; pw < 8; pw++) {
        #pragma unroll
        for (int rp = 0; rp < 8; rp++) {
            const int p = pw * 8 + rp;
            float* buf = rowbuf[rp & 1];
            if (w == pw) { buf[l] = pr[rp][0]; buf[l + 32] = pr[rp][1]; }
            __syncthreads();
            const float r0 = buf[l], r1 = buf[l + 32];
            const float pinv = 1.0f / buf[p];
            const bool hi = (p >= 32);
            const int pl = p & 31;
            #pragma unroll
            for (int r = 0; r < 8; r++) {
                const float src = hi ? pr[r][1] : pr[r][0];
                const float colv = __shfl_sync(0xffffffffu, src, pl);
                if (r == rp && w == pw) {
                    pr[r][0] = r0 * pinv;
                    pr[r][1] = r1 * pinv;
                    if (l == pl) { if (hi) pr[r][1] = pinv; else pr[r][0] = pinv; }
                } else {
                    const float sc = colv * pinv;
                    pr[r][0] -= sc * r0;
                    pr[r][1] -= sc * r1;
                    if (l == pl) { if (hi) pr[r][1] = -sc; else pr[r][0] = -sc; }
                }
            }
        }
    }
}

// ---------------- global max + argmax ----------------
__global__ void k_max(const float* __restrict__ s) {
    __shared__ unsigned long long sm[256];
    unsigned long long best = 0ULL;
    const size_t total = (size_t)BB * SS * SS;
    for (size_t i = (size_t)blockIdx.x * blockDim.x + threadIdx.x; i < total;
         i += (size_t)gridDim.x * blockDim.x) {
        unsigned long long c = ((unsigned long long)enc_f(s[i]) << 32) | (unsigned int)i;
        if (c > best) best = c;
    }
    sm[threadIdx.x] = best;
    __syncthreads();
    for (int o = 128; o > 0; o >>= 1) {
        if (threadIdx.x < o && sm[threadIdx.x + o] > sm[threadIdx.x]) sm[threadIdx.x] = sm[threadIdx.x + o];
        __syncthreads();
    }
    if (threadIdx.x == 0) atomicMax(&g_maxkey, sm[0]);
}

// ---------------- fused rowsum + build: one block per M row ----------------
__global__ void __launch_bounds__(256) k_build2(const float* __restrict__ s) {
    __shared__ float e[1024];
    __shared__ double sd[256];
    const int p = blockIdx.x;            // 0..1023
    const int b = blockIdx.y;
    const int tid = threadIdx.x;
    float* Mrow = g_M + ((size_t)b << 20) + ((size_t)p << 10);

    if (p == 1023) {
        for (int q = tid; q < 1024; q += 256) Mrow[q] = (q == 1023) ? 1.0f : 0.0f;
        return;
    }
    const float m = get_m();
    const float* srow = s + ((size_t)b << 20) + ((size_t)(p + 1) << 10);
    float4 v = *(const float4*)(srow + tid * 4);
    float e0 = expf(v.x - m), e1 = expf(v.y - m), e2 = expf(v.z - m), e3 = expf(v.w - m);
    e[tid * 4 + 0] = e0; e[tid * 4 + 1] = e1; e[tid * 4 + 2] = e2; e[tid * 4 + 3] = e3;
    sd[tid] = (double)e0 + (double)e1 + (double)e2 + (double)e3;
    __syncthreads();
    for (int o = 128; o > 0; o >>= 1) {
        if (tid < o) sd[tid] += sd[tid + o];
        __syncthreads();
    }
    const double r = sd[0];
    for (int q = tid; q < 1024; q += 256) {
        float out;
        if (q == 1023)      out = 0.0f;
        else if (q == p)    out = (float)(r - (double)e[p + 1]);
        else                out = -e[q + 1];
        Mrow[q] = out;
    }
}

// ---------------- initial pivot inversion: g_P = inv(M(0,0)) ----------------
__global__ void __launch_bounds__(256) k_inv0() {
    __shared__ float rowbuf[2][64];
    const int b = blockIdx.x, tid = threadIdx.x;
    const int w = tid >> 5, l = tid & 31;
    float pr[8][2];
    const float* Pg = g_M + ((size_t)b << 20);
    #pragma unroll
    for (int r = 0; r < 8; r++) {
        pr[r][0] = Pg[((size_t)(w * 8 + r) << 10) + l];
        pr[r][1] = Pg[((size_t)(w * 8 + r) << 10) + l + 32];
    }
    gj64(pr, rowbuf, w, l);
    float* Pd = g_P + ((size_t)b << 12);
    #pragma unroll
    for (int r = 0; r < 8; r++) {
        Pd[(w * 8 + r) * NB + l]      = pr[r][0];
        Pd[(w * 8 + r) * NB + l + 32] = pr[r][1];
    }
}

// =====================================================================
// Panel kernel (R8, proven): grid (30, BB)
// =====================================================================
__global__ void __launch_bounds__(256) k_panel(int k) {
    __shared__ float AsT[2][32 * 68];
    __shared__ float Bs [2][32 * 68];
    const int b = blockIdx.y;
    const int x = blockIdx.x;
    const int tid = threadIdx.x;
    const size_t base = (size_t)b << 20;
    const int role = (x < 15) ? 0 : 1;
    const float* Pd = g_P + ((size_t)b << 12);

    const int ai0 = tid >> 3, ac = (tid & 7) << 2;
    const int ai1 = ai0 + 32;
    const int bk0 = tid >> 4, bj = (tid & 15) << 2;
    const int bk1 = bk0 + 16;

    int ib = k, jb = k;
    const float* Ag;
    const float* Bg;
    float* Sg = 0;
    int bstride;
    if (role == 0) {
        jb = x + (x >= k);
        Ag = Pd;
        Bg = g_M + base + (((size_t)k * NB) << 10) + (size_t)jb * NB;
        Sg = g_S + ((size_t)b << 16) + (size_t)jb * NB;
        bstride = 1024;
    } else {
        ib = (x - 15) + ((x - 15) >= k);
        Ag = g_M + base + (((size_t)ib * NB) << 10) + (size_t)k * NB;
        Bg = Pd;
        bstride = NB;
    }
    const int astride = (role == 0) ? NB : 1024;

    float4 A0 = *(const float4*)(Ag + (size_t)ai0 * astride + ac);
    float4 A1 = *(const float4*)(Ag + (size_t)ai1 * astride + ac);
    float4 B0 = *(const float4*)(Bg + (size_t)bk0 * bstride + bj);
    float4 B1 = *(const float4*)(Bg + (size_t)bk1 * bstride + bj);
    AsT[0][(ac + 0) * 68 + ai0] = A0.x; AsT[0][(ac + 1) * 68 + ai0] = A0.y;
    AsT[0][(ac + 2) * 68 + ai0] = A0.z; AsT[0][(ac + 3) * 68 + ai0] = A0.w;
    AsT[0][(ac + 0) * 68 + ai1] = A1.x; AsT[0][(ac + 1) * 68 + ai1] = A1.y;
    AsT[0][(ac + 2) * 68 + ai1] = A1.z; AsT[0][(ac + 3) * 68 + ai1] = A1.w;
    *(float4*)(&Bs[0][bk0 * 68 + bj]) = B0;
    *(float4*)(&Bs[0][bk1 * 68 + bj]) = B1;
    if (role == 0) {
        *(float4*)(Sg + (size_t)bk0 * SS + bj) = B0;
        *(float4*)(Sg + (size_t)bk1 * SS + bj) = B1;
    }
    A0 = *(const float4*)(Ag + (size_t)ai0 * astride + 32 + ac);
    A1 = *(const float4*)(Ag + (size_t)ai1 * astride + 32 + ac);
    B0 = *(const float4*)(Bg + (size_t)(bk0 + 32) * bstride + bj);
    B1 = *(const float4*)(Bg + (size_t)(bk1 + 32) * bstride + bj);
    __syncthreads();

    const int j0 = (tid & 15) * 4;
    const int i0 = (tid >> 4) * 4;
    float acc[4][4] = {};
    #pragma unroll 8
    for (int kk = 0; kk < 32; kk++) {
        const float4 a = *(const float4*)(&AsT[0][kk * 68 + i0]);
        const float4 v = *(const float4*)(&Bs [0][kk * 68 + j0]);
        acc[0][0] += a.x * v.x; acc[0][1] += a.x * v.y; acc[0][2] += a.x * v.z; acc[0][3] += a.x * v.w;
        acc[1][0] += a.y * v.x; acc[1][1] += a.y * v.y; acc[1][2] += a.y * v.z; acc[1][3] += a.y * v.w;
        acc[2][0] += a.z * v.x; acc[2][1] += a.z * v.y; acc[2][2] += a.z * v.z; acc[2][3] += a.z * v.w;
        acc[3][0] += a.w * v.x; acc[3][1] += a.w * v.y; acc[3][2] += a.w * v.z; acc[3][3] += a.w * v.w;
    }
    AsT[1][(ac + 0) * 68 + ai0] = A0.x; AsT[1][(ac + 1) * 68 + ai0] = A0.y;
    AsT[1][(ac + 2) * 68 + ai0] = A0.z; AsT[1][(ac + 3) * 68 + ai0] = A0.w;
    AsT[1][(ac + 0) * 68 + ai1] = A1.x; AsT[1][(ac + 1) * 68 + ai1] = A1.y;
    AsT[1][(ac + 2) * 68 + ai1] = A1.z; AsT[1][(ac + 3) * 68 + ai1] = A1.w;
    *(float4*)(&Bs[1][bk0 * 68 + bj]) = B0;
    *(float4*)(&Bs[1][bk1 * 68 + bj]) = B1;
    if (role == 0) {
        *(float4*)(Sg + (size_t)(bk0 + 32) * SS + bj) = B0;
        *(float4*)(Sg + (size_t)(bk1 + 32) * SS + bj) = B1;
    }
    __syncthreads();
    #pragma unroll 8
    for (int kk = 0; kk < 32; kk++) {
        const float4 a = *(const float4*)(&AsT[1][kk * 68 + i0]);
        const float4 v = *(const float4*)(&Bs [1][kk * 68 + j0]);
        acc[0][0] += a.x * v.x; acc[0][1] += a.x * v.y; acc[0][2] += a.x * v.z; acc[0][3] += a.x * v.w;
        acc[1][0] += a.y * v.x; acc[1][1] += a.y * v.y; acc[1][2] += a.y * v.z; acc[1][3] += a.y * v.w;
        acc[2][0] += a.z * v.x; acc[2][1] += a.z * v.y; acc[2][2] += a.z * v.z; acc[2][3] += a.z * v.w;
        acc[3][0] += a.w * v.x; acc[3][1] += a.w * v.y; acc[3][2] += a.w * v.z; acc[3][3] += a.w * v.w;
    }

    float* Cg = (role == 0)
        ? g_M + base + (((size_t)k  * NB) << 10) + (size_t)jb * NB
        : g_M + base + (((size_t)ib * NB) << 10) + (size_t)k  * NB;
    const float sgn = (role == 0) ? 1.0f : -1.0f;
    #pragma unroll
    for (int r = 0; r < 4; r++) {
        float4 c;
        c.x = sgn * acc[r][0]; c.y = sgn * acc[r][1];
        c.z = sgn * acc[r][2]; c.w = sgn * acc[r][3];
        *(float4*)(Cg + ((size_t)(i0 + r) << 10) + j0) = c;
    }
}

// =====================================================================
// Trailing update, FFMA2 (f32x2), 128x128 tile = 2x2 of 64-blocks.
// grid (8, 8, BB): X -> jb pair, Y -> ib pair; edge halves masked.
// Per thread: 8x8 outputs as 32 f32x2 accumulators.
// K=64 in two 32-phases, single smem buffer + register prefetch.
// Special CTA (0,0): installs P^-1(k) into g_M(k,k); after epilogue inverts
// tile (k+1,k+1) (fully owned by this CTA's quadrant (0,0)) -> g_P.
// =====================================================================
__global__ void __launch_bounds__(256) k_trail128(int k) {
    __shared__ float AsT[32 * 132];   // AsT[kk][i], i 0..127
    __shared__ float Bs [32 * 132];   // Bs [kk][j], j 0..127
    __shared__ float rowbuf[2][64];
    const int tid = threadIdx.x;
    const int b = blockIdx.z;
    const int X = blockIdx.x, Y = blockIdx.y;
    const size_t base = (size_t)b << 20;
    const int ib0 = (k + 1 + 2 * Y) & 15, ib1 = (k + 2 + 2 * Y) & 15;
    const int jb0 = (k + 1 + 2 * X) & 15, jb1 = (k + 2 + 2 * X) & 15;
    const bool iv1 = (2 * Y + 1) < 15, jv1 = (2 * X + 1) < 15;
    const bool special = (X == 0 && Y == 0);

    if (special) {   // install P^-1(k); tile (k,k) is never a valid operand this step
        const float* Pd = g_P + ((size_t)b << 12);
        float* Pg = g_M + base + (((size_t)k * NB) << 10) + (size_t)k * NB;
        #pragma unroll
        for (int f = tid; f < 1024; f += 256) {
            const int r = f >> 4, c4 = (f & 15) << 2;
            *(float4*)(Pg + ((size_t)r << 10) + c4) = *(const float4*)(Pd + r * NB + c4);
        }
    }

    const float* A0g = g_M + base + (((size_t)ib0 * NB) << 10) + (size_t)k * NB;
    const float* A1g = g_M + base + (((size_t)ib1 * NB) << 10) + (size_t)k * NB;
    const float* Sg  = g_S + ((size_t)b << 16);

    // ---- phase 0 fill ----
    #pragma unroll
    for (int t = 0; t < 4; t++) {
        const int f = tid + 256 * t;
        const int ai = f >> 3, ac4 = (f & 7) << 2;
        const float* Ar = (ai < 64) ? (A0g + ((size_t)ai << 10)) : (A1g + ((size_t)(ai - 64) << 10));
        float4 v = *(const float4*)(Ar + ac4);
        AsT[(ac4 + 0) * 132 + ai] = v.x;
        AsT[(ac4 + 1) * 132 + ai] = v.y;
        AsT[(ac4 + 2) * 132 + ai] = v.z;
        AsT[(ac4 + 3) * 132 + ai] = v.w;
        const int kk = f >> 5, j4 = (f & 31) << 2;
        const int jbb = (j4 < 64) ? jb0 : jb1;
        float4 w = *(const float4*)(Sg + (size_t)kk * SS + jbb * NB + (j4 & 63));
        *(float4*)&Bs[kk * 132 + j4] = w;
    }
    // ---- phase 1 prefetch -> registers ----
    float4 pa[4], pb[4];
    #pragma unroll
    for (int t = 0; t < 4; t++) {
        const int f = tid + 256 * t;
        const int ai = f >> 3, ac4 = (f & 7) << 2;
        const float* Ar = (ai < 64) ? (A0g + ((size_t)ai << 10)) : (A1g + ((size_t)(ai - 64) << 10));
        pa[t] = *(const float4*)(Ar + 32 + ac4);
        const int kk = f >> 5, j4 = (f & 31) << 2;
        const int jbb = (j4 < 64) ? jb0 : jb1;
        pb[t] = *(const float4*)(Sg + (size_t)(kk + 32) * SS + jbb * NB + (j4 & 63));
    }
    __syncthreads();

    const int i0 = (tid >> 4) * 8;   // 0..120
    const int j0 = (tid & 15) * 8;   // 0..120
    unsigned long long acc[8][4];
    #pragma unroll
    for (int r = 0; r < 8; r++)
        #pragma unroll
        for (int c = 0; c < 4; c++) acc[r][c] = 0ULL;

    #pragma unroll 4
    for (int kk = 0; kk < 32; kk++) {
        const float4 a0 = *(const float4*)&AsT[kk * 132 + i0];
        const float4 a1 = *(const float4*)&AsT[kk * 132 + i0 + 4];
        const ulonglong2 bA = *(const ulonglong2*)&Bs[kk * 132 + j0];
        const ulonglong2 bB = *(const ulonglong2*)&Bs[kk * 132 + j0 + 4];
        unsigned long long ad[8];
        ad[0] = dup2(a0.x); ad[1] = dup2(a0.y); ad[2] = dup2(a0.z); ad[3] = dup2(a0.w);
        ad[4] = dup2(a1.x); ad[5] = dup2(a1.y); ad[6] = dup2(a1.z); ad[7] = dup2(a1.w);
        #pragma unroll
        for (int r = 0; r < 8; r++) {
            ffma2(acc[r][0], ad[r], bA.x);
            ffma2(acc[r][1], ad[r], bA.y);
            ffma2(acc[r][2], ad[r], bB.x);
            ffma2(acc[r][3], ad[r], bB.y);
        }
    }
    __syncthreads();
    // ---- phase 1 store -> smem ----
    #pragma unroll
    for (int t = 0; t < 4; t++) {
        const int f = tid + 256 * t;
        const int ai = f >> 3, ac4 = (f & 7) << 2;
        AsT[(ac4 + 0) * 132 + ai] = pa[t].x;
        AsT[(ac4 + 1) * 132 + ai] = pa[t].y;
        AsT[(ac4 + 2) * 132 + ai] = pa[t].z;
        AsT[(ac4 + 3) * 132 + ai] = pa[t].w;
        const int kk = f >> 5, j4 = (f & 31) << 2;
        *(float4*)&Bs[kk * 132 + j4] = pb[t];
    }
    __syncthreads();
    #pragma unroll 4
    for (int kk = 0; kk < 32; kk++) {
        const float4 a0 = *(const float4*)&AsT[kk * 132 + i0];
        const float4 a1 = *(const float4*)&AsT[kk * 132 + i0 + 4];
        const ulonglong2 bA = *(const ulonglong2*)&Bs[kk * 132 + j0];
        const ulonglong2 bB = *(const ulonglong2*)&Bs[kk * 132 + j0 + 4];
        unsigned long long ad[8];
        ad[0] = dup2(a0.x); ad[1] = dup2(a0.y); ad[2] = dup2(a0.z); ad[3] = dup2(a0.w);
        ad[4] = dup2(a1.x); ad[5] = dup2(a1.y); ad[6] = dup2(a1.z); ad[7] = dup2(a1.w);
        #pragma unroll
        for (int r = 0; r < 8; r++) {
            ffma2(acc[r][0], ad[r], bA.x);
            ffma2(acc[r][1], ad[r], bA.y);
            ffma2(acc[r][2], ad[r], bB.x);
            ffma2(acc[r][3], ad[r], bB.y);
        }
    }

    // ---- epilogue: C += acc (each thread's 8x8 lies in ONE 64-block pair) ----
    const bool valid = (i0 < 64 || iv1) && (j0 < 64 || jv1);
    if (valid) {
        const int iblk = (i0 < 64) ? ib0 : ib1;
        const int jblk = (j0 < 64) ? jb0 : jb1;
        float* Cg = g_M + base + (((size_t)(iblk * NB + (i0 & 63))) << 10) + jblk * NB + (j0 & 63);
        #pragma unroll
        for (int r = 0; r < 8; r++) {
            float* row = Cg + ((size_t)r << 10);
            float4 c0 = *(float4*)(row);
            float4 c1 = *(float4*)(row + 4);
            const float2* af = (const float2*)acc[r];
            c0.x += af[0].x; c0.y += af[0].y; c0.z += af[1].x; c0.w += af[1].y;
            c1.x += af[2].x; c1.y += af[2].y; c1.z += af[3].x; c1.w += af[3].y;
            *(float4*)(row)     = c0;
            *(float4*)(row + 4) = c1;
        }
    }
    __syncthreads();

    // ---- fused next-pivot inversion: tile (k+1,k+1) fully owned by CTA (0,0) ----
    if (special && k < NSTEP - 1) {
        const int kn = (k + 1) & 15;
        const float* Pg = g_M + base + (((size_t)kn * NB) << 10) + (size_t)kn * NB;
        const int w = tid >> 5, l = tid & 31;
        float pr[8][2];
        #pragma unroll
        for (int r = 0; r < 8; r++) {
            pr[r][0] = Pg[((size_t)(w * 8 + r) << 10) + l];
            pr[r][1] = Pg[((size_t)(w * 8 + r) << 10) + l + 32];
        }
        gj64(pr, rowbuf, w, l);
        float* Pd = g_P + ((size_t)b << 12);
        #pragma unroll
        for (int r = 0; r < 8; r++) {
            Pd[(w * 8 + r) * NB + l]      = pr[r][0];
            Pd[(w * 8 + r) * NB + l + 32] = pr[r][1];
        }
    }
}

// ---------------- diag extraction: g_diag[b][i] = Minv[i][i] ----------------
__global__ void k_diag() {
    const int i = blockIdx.x * 256 + threadIdx.x;
    const int b = blockIdx.y;
    g_diag[b * SS + i] = g_M[((size_t)b << 20) + ((size_t)i << 10) + i];
}

// ---------------- assemble probs (fused transpose) ----------------
__global__ void k_out2(const float* __restrict__ s, float* __restrict__ out) {
    __shared__ float tile[32][33];
    __shared__ float sdiag[32];
    const int b  = blockIdx.z;
    const int p0 = blockIdx.y * 32;
    const int q0 = blockIdx.x * 32;
    const int tx = threadIdx.x, ty = threadIdx.y;
    const size_t base = (size_t)b << 20;

    for (int r = ty; r < 32; r += 8) {
        const int q = q0 + r, p = p0 + tx;
        float v = 0.0f;
        if (q >= 1 && p >= 1) v = g_M[base + ((size_t)(q - 1) << 10) + (p - 1)];
        tile[r][tx] = v;
    }
    if (ty == 0) {
        const int p = p0 + tx;
        sdiag[tx] = (p >= 1) ? g_diag[b * SS + p - 1] : 0.0f;
    }
    __syncthreads();

    const float m = get_m();
    const unsigned long long key = g_maxkey;
    const unsigned int amax = (unsigned int)(key & 0xffffffffu);
    for (int r = ty; r < 32; r += 8) {
        const int p = p0 + r, q = q0 + tx;
        const size_t t = base + ((size_t)p << 10) + q;
        float v = 0.0f;
        if (p >= 1) {
            const float sub = (q >= 1) ? tile[tx][r] : 0.0f;
            v = expf(s[t] - m) * (sdiag[r] - sub);
        }
        if ((unsigned int)t == amax) v += 16.0f;
        out[t] = v;
    }
}

extern "C" void kernel_launch(void* const* d_in, const int* in_sizes, int n_in,
                              void* d_out, int out_size) {
    (void)in_sizes; (void)n_in; (void)out_size;
    const float* s = (const float*)d_in[0];
    float* out = (float*)d_out;

    k_max<<<2048, 256>>>(s);
    k_build2<<<dim3(1024, BB), 256>>>(s);
    k_inv0<<<BB, 256>>>();

    for (int k = 0; k < NSTEP; k++) {
        k_panel<<<dim3(30, BB), 256>>>(k);
        k_trail128<<<dim3(8, 8, BB), 256>>>(k);
    }

    k_diag<<<dim3(4, BB), 256>>>();
    k_out2<<<dim3(32, 32, BB), dim3(32, 8)>>>(s, out);
}

// round 10
// speedup vs baseline: 1.0603x; 1.0603x over previous
#include <cuda_runtime.h>
#include <math.h>
#include <stdint.h>

#define BB 16
#define SS 1024
#define NB 64
#define NSTEP 16   // 1024/64

// ---- static device scratch (allocation-free) ----
static __device__ float g_M [(size_t)BB * SS * SS];   // 64 MB: padded minors -> inverses
static __device__ float g_S [(size_t)BB * NB * SS];   // 4 MB: stashed old row stripe
static __device__ float g_P [(size_t)BB * NB * NB];   // 256 KB: current pivot inverse P^-1
static __device__ float g_diag[BB * SS];              // diag(Minv)
static __device__ unsigned long long g_maxkey;        // (sortable-key<<32)|argmax

__device__ __forceinline__ unsigned int enc_f(float v) {
    unsigned int u = __float_as_uint(v);
    return (u & 0x80000000u) ? ~u : (u | 0x80000000u);
}
__device__ __forceinline__ float dec_f(unsigned int k) {
    unsigned int u = (k & 0x80000000u) ? (k ^ 0x80000000u) : ~k;
    return __uint_as_float(u);
}
__device__ __forceinline__ float get_m() { return dec_f((unsigned int)(g_maxkey >> 32)); }

// ---- packed f32x2 helpers ----
__device__ __forceinline__ unsigned long long dup2(float x) {
    unsigned long long r;
    asm("mov.b64 %0, {%1, %1};" : "=l"(r) : "f"(x));
    return r;
}
__device__ __forceinline__ void ffma2(unsigned long long& d, unsigned long long a,
                                      unsigned long long b) {
    asm("fma.rn.f32x2 %0, %1, %2, %0;" : "+l"(d) : "l"(a), "l"(b));
}

// ---- cp.async helpers ----
__device__ __forceinline__ uint32_t smem_u32(const void* p) {
    uint32_t a;
    asm("{ .reg .u64 t; cvta.to.shared.u64 t, %1; cvt.u32.u64 %0, t; }" : "=r"(a) : "l"(p));
    return a;
}
__device__ __forceinline__ void cp16(uint32_t dst, const void* src) {
    asm volatile("cp.async.ca.shared.global [%0], [%1], 16;" :: "r"(dst), "l"(src));
}
#define CP_COMMIT() asm volatile("cp.async.commit_group;" ::: "memory")

// ---- register Gauss-Jordan inversion of a 64x64 block (8 warps x 8 rows x 2 cols/lane) ----
__device__ __forceinline__ void gj64(float pr[8][2], float (*rowbuf)[64], int w, int l) {
    for (int pw = 0; pw < 8; pw++) {
        #pragma unroll
        for (int rp = 0; rp < 8; rp++) {
            const int p = pw * 8 + rp;
            float* buf = rowbuf[rp & 1];
            if (w == pw) { buf[l] = pr[rp][0]; buf[l + 32] = pr[rp][1]; }
            __syncthreads();
            const float r0 = buf[l], r1 = buf[l + 32];
            const float pinv = 1.0f / buf[p];
            const bool hi = (p >= 32);
            const int pl = p & 31;
            #pragma unroll
            for (int r = 0; r < 8; r++) {
                const float src = hi ? pr[r][1] : pr[r][0];
                const float colv = __shfl_sync(0xffffffffu, src, pl);
                if (r == rp && w == pw) {
                    pr[r][0] = r0 * pinv;
                    pr[r][1] = r1 * pinv;
                    if (l == pl) { if (hi) pr[r][1] = pinv; else pr[r][0] = pinv; }
                } else {
                    const float sc = colv * pinv;
                    pr[r][0] -= sc * r0;
                    pr[r][1] -= sc * r1;
                    if (l == pl) { if (hi) pr[r][1] = -sc; else pr[r][0] = -sc; }
                }
            }
        }
    }
}

// ---------------- global max + argmax ----------------
__global__ void k_max(const float* __restrict__ s) {
    __shared__ unsigned long long sm[256];
    unsigned long long best = 0ULL;
    const size_t total = (size_t)BB * SS * SS;
    for (size_t i = (size_t)blockIdx.x * blockDim.x + threadIdx.x; i < total;
         i += (size_t)gridDim.x * blockDim.x) {
        unsigned long long c = ((unsigned long long)enc_f(s[i]) << 32) | (unsigned int)i;
        if (c > best) best = c;
    }
    sm[threadIdx.x] = best;
    __syncthreads();
    for (int o = 128; o > 0; o >>= 1) {
        if (threadIdx.x < o && sm[threadIdx.x + o] > sm[threadIdx.x]) sm[threadIdx.x] = sm[threadIdx.x + o];
        __syncthreads();
    }
    if (threadIdx.x == 0) atomicMax(&g_maxkey, sm[0]);
}

// ---------------- fused rowsum + build: one block per M row ----------------
__global__ void __launch_bounds__(256) k_build2(const float* __restrict__ s) {
    __shared__ float e[1024];
    __shared__ double sd[256];
    const int p = blockIdx.x;            // 0..1023
    const int b = blockIdx.y;
    const int tid = threadIdx.x;
    float* Mrow = g_M + ((size_t)b << 20) + ((size_t)p << 10);

    if (p == 1023) {
        for (int q = tid; q < 1024; q += 256) Mrow[q] = (q == 1023) ? 1.0f : 0.0f;
        return;
    }
    const float m = get_m();
    const float* srow = s + ((size_t)b << 20) + ((size_t)(p + 1) << 10);
    float4 v = *(const float4*)(srow + tid * 4);
    float e0 = expf(v.x - m), e1 = expf(v.y - m), e2 = expf(v.z - m), e3 = expf(v.w - m);
    e[tid * 4 + 0] = e0; e[tid * 4 + 1] = e1; e[tid * 4 + 2] = e2; e[tid * 4 + 3] = e3;
    sd[tid] = (double)e0 + (double)e1 + (double)e2 + (double)e3;
    __syncthreads();
    for (int o = 128; o > 0; o >>= 1) {
        if (tid < o) sd[tid] += sd[tid + o];
        __syncthreads();
    }
    const double r = sd[0];
    for (int q = tid; q < 1024; q += 256) {
        float out;
        if (q == 1023)      out = 0.0f;
        else if (q == p)    out = (float)(r - (double)e[p + 1]);
        else                out = -e[q + 1];
        Mrow[q] = out;
    }
}

// ---------------- initial pivot inversion: g_P = inv(M(0,0)) ----------------
__global__ void __launch_bounds__(256) k_inv0() {
    __shared__ float rowbuf[2][64];
    const int b = blockIdx.x, tid = threadIdx.x;
    const int w = tid >> 5, l = tid & 31;
    float pr[8][2];
    const float* Pg = g_M + ((size_t)b << 20);
    #pragma unroll
    for (int r = 0; r < 8; r++) {
        pr[r][0] = Pg[((size_t)(w * 8 + r) << 10) + l];
        pr[r][1] = Pg[((size_t)(w * 8 + r) << 10) + l + 32];
    }
    gj64(pr, rowbuf, w, l);
    float* Pd = g_P + ((size_t)b << 12);
    #pragma unroll
    for (int r = 0; r < 8; r++) {
        Pd[(w * 8 + r) * NB + l]      = pr[r][0];
        Pd[(w * 8 + r) * NB + l + 32] = pr[r][1];
    }
}

// =====================================================================
// Panel kernel (R8, proven): grid (30, BB)
// =====================================================================
__global__ void __launch_bounds__(256) k_panel(int k) {
    __shared__ float AsT[2][32 * 68];
    __shared__ float Bs [2][32 * 68];
    const int b = blockIdx.y;
    const int x = blockIdx.x;
    const int tid = threadIdx.x;
    const size_t base = (size_t)b << 20;
    const int role = (x < 15) ? 0 : 1;
    const float* Pd = g_P + ((size_t)b << 12);

    const int ai0 = tid >> 3, ac = (tid & 7) << 2;
    const int ai1 = ai0 + 32;
    const int bk0 = tid >> 4, bj = (tid & 15) << 2;
    const int bk1 = bk0 + 16;

    int ib = k, jb = k;
    const float* Ag;
    const float* Bg;
    float* Sg = 0;
    int bstride;
    if (role == 0) {
        jb = x + (x >= k);
        Ag = Pd;
        Bg = g_M + base + (((size_t)k * NB) << 10) + (size_t)jb * NB;
        Sg = g_S + ((size_t)b << 16) + (size_t)jb * NB;
        bstride = 1024;
    } else {
        ib = (x - 15) + ((x - 15) >= k);
        Ag = g_M + base + (((size_t)ib * NB) << 10) + (size_t)k * NB;
        Bg = Pd;
        bstride = NB;
    }
    const int astride = (role == 0) ? NB : 1024;

    float4 A0 = *(const float4*)(Ag + (size_t)ai0 * astride + ac);
    float4 A1 = *(const float4*)(Ag + (size_t)ai1 * astride + ac);
    float4 B0 = *(const float4*)(Bg + (size_t)bk0 * bstride + bj);
    float4 B1 = *(const float4*)(Bg + (size_t)bk1 * bstride + bj);
    AsT[0][(ac + 0) * 68 + ai0] = A0.x; AsT[0][(ac + 1) * 68 + ai0] = A0.y;
    AsT[0][(ac + 2) * 68 + ai0] = A0.z; AsT[0][(ac + 3) * 68 + ai0] = A0.w;
    AsT[0][(ac + 0) * 68 + ai1] = A1.x; AsT[0][(ac + 1) * 68 + ai1] = A1.y;
    AsT[0][(ac + 2) * 68 + ai1] = A1.z; AsT[0][(ac + 3) * 68 + ai1] = A1.w;
    *(float4*)(&Bs[0][bk0 * 68 + bj]) = B0;
    *(float4*)(&Bs[0][bk1 * 68 + bj]) = B1;
    if (role == 0) {
        *(float4*)(Sg + (size_t)bk0 * SS + bj) = B0;
        *(float4*)(Sg + (size_t)bk1 * SS + bj) = B1;
    }
    A0 = *(const float4*)(Ag + (size_t)ai0 * astride + 32 + ac);
    A1 = *(const float4*)(Ag + (size_t)ai1 * astride + 32 + ac);
    B0 = *(const float4*)(Bg + (size_t)(bk0 + 32) * bstride + bj);
    B1 = *(const float4*)(Bg + (size_t)(bk1 + 32) * bstride + bj);
    __syncthreads();

    const int j0 = (tid & 15) * 4;
    const int i0 = (tid >> 4) * 4;
    float acc[4][4] = {};
    #pragma unroll 8
    for (int kk = 0; kk < 32; kk++) {
        const float4 a = *(const float4*)(&AsT[0][kk * 68 + i0]);
        const float4 v = *(const float4*)(&Bs [0][kk * 68 + j0]);
        acc[0][0] += a.x * v.x; acc[0][1] += a.x * v.y; acc[0][2] += a.x * v.z; acc[0][3] += a.x * v.w;
        acc[1][0] += a.y * v.x; acc[1][1] += a.y * v.y; acc[1][2] += a.y * v.z; acc[1][3] += a.y * v.w;
        acc[2][0] += a.z * v.x; acc[2][1] += a.z * v.y; acc[2][2] += a.z * v.z; acc[2][3] += a.z * v.w;
        acc[3][0] += a.w * v.x; acc[3][1] += a.w * v.y; acc[3][2] += a.w * v.z; acc[3][3] += a.w * v.w;
    }
    AsT[1][(ac + 0) * 68 + ai0] = A0.x; AsT[1][(ac + 1) * 68 + ai0] = A0.y;
    AsT[1][(ac + 2) * 68 + ai0] = A0.z; AsT[1][(ac + 3) * 68 + ai0] = A0.w;
    AsT[1][(ac + 0) * 68 + ai1] = A1.x; AsT[1][(ac + 1) * 68 + ai1] = A1.y;
    AsT[1][(ac + 2) * 68 + ai1] = A1.z; AsT[1][(ac + 3) * 68 + ai1] = A1.w;
    *(float4*)(&Bs[1][bk0 * 68 + bj]) = B0;
    *(float4*)(&Bs[1][bk1 * 68 + bj]) = B1;
    if (role == 0) {
        *(float4*)(Sg + (size_t)(bk0 + 32) * SS + bj) = B0;
        *(float4*)(Sg + (size_t)(bk1 + 32) * SS + bj) = B1;
    }
    __syncthreads();
    #pragma unroll 8
    for (int kk = 0; kk < 32; kk++) {
        const float4 a = *(const float4*)(&AsT[1][kk * 68 + i0]);
        const float4 v = *(const float4*)(&Bs [1][kk * 68 + j0]);
        acc[0][0] += a.x * v.x; acc[0][1] += a.x * v.y; acc[0][2] += a.x * v.z; acc[0][3] += a.x * v.w;
        acc[1][0] += a.y * v.x; acc[1][1] += a.y * v.y; acc[1][2] += a.y * v.z; acc[1][3] += a.y * v.w;
        acc[2][0] += a.z * v.x; acc[2][1] += a.z * v.y; acc[2][2] += a.z * v.z; acc[2][3] += a.z * v.w;
        acc[3][0] += a.w * v.x; acc[3][1] += a.w * v.y; acc[3][2] += a.w * v.z; acc[3][3] += a.w * v.w;
    }

    float* Cg = (role == 0)
        ? g_M + base + (((size_t)k  * NB) << 10) + (size_t)jb * NB
        : g_M + base + (((size_t)ib * NB) << 10) + (size_t)k  * NB;
    const float sgn = (role == 0) ? 1.0f : -1.0f;
    #pragma unroll
    for (int r = 0; r < 4; r++) {
        float4 c;
        c.x = sgn * acc[r][0]; c.y = sgn * acc[r][1];
        c.z = sgn * acc[r][2]; c.w = sgn * acc[r][3];
        *(float4*)(Cg + ((size_t)(i0 + r) << 10) + j0) = c;
    }
}

// =====================================================================
// Trailing update, FFMA2 (f32x2), 128x128 tile, cp.async double-buffered.
// grid (8, 8, BB). K=64 as 4 phases of 16. 8x8 acc per thread (32 f32x2).
// A stored untransposed As[i][kk] (broadcast LDS.32 reads); B row-major.
// __launch_bounds__(256,2) forces <=128 regs -> 2 CTAs/SM.
// Special CTA (0,0): installs P^-1(k) into g_M(k,k); after epilogue inverts
// tile (k+1,k+1) -> g_P.
// =====================================================================
__global__ void __launch_bounds__(256, 2) k_trail128(int k) {
    __shared__ __align__(16) float As[2 * 128 * 16];   // As[h][i*16 + kk]
    __shared__ __align__(16) float Bs[2 * 16 * 128];   // Bs[h][kk*128 + j]
    __shared__ float rowbuf[2][64];
    const int tid = threadIdx.x;
    const int b = blockIdx.z;
    const int X = blockIdx.x, Y = blockIdx.y;
    const size_t base = (size_t)b << 20;
    const int ib0 = (k + 1 + 2 * Y) & 15, ib1 = (k + 2 + 2 * Y) & 15;
    const int jb0 = (k + 1 + 2 * X) & 15, jb1 = (k + 2 + 2 * X) & 15;
    const bool iv1 = (2 * Y + 1) < 15, jv1 = (2 * X + 1) < 15;
    const bool special = (X == 0 && Y == 0);

    if (special) {   // install P^-1(k); tile (k,k) is not an operand this step
        const float* Pd = g_P + ((size_t)b << 12);
        float* Pg = g_M + base + (((size_t)k * NB) << 10) + (size_t)k * NB;
        #pragma unroll
        for (int f = tid; f < 1024; f += 256) {
            const int r = f >> 4, c4 = (f & 15) << 2;
            *(float4*)(Pg + ((size_t)r << 10) + c4) = *(const float4*)(Pd + r * NB + c4);
        }
    }

    const float* A0g = g_M + base + (((size_t)ib0 * NB) << 10) + (size_t)k * NB;
    const float* A1g = g_M + base + (((size_t)ib1 * NB) << 10) + (size_t)k * NB;
    const float* Sg  = g_S + ((size_t)b << 16);

    // per-thread cp.async coordinates
    const int ia = tid >> 2, ca = (tid & 3) << 2;     // A: rows ia (0..63) and ia+64
    const int kb = tid >> 5, j4 = (tid & 31) << 2;    // B: kk rows kb, kb+8
    const int jbb = (j4 < 64) ? jb0 : jb1;
    const float* srcA0 = A0g + ((size_t)ia << 10) + ca;
    const float* srcA1 = A1g + ((size_t)ia << 10) + ca;
    const float* srcB  = Sg + (size_t)kb * SS + jbb * NB + (j4 & 63);
    const uint32_t As_u32 = smem_u32(As);
    const uint32_t Bs_u32 = smem_u32(Bs);
    const uint32_t dA0 = As_u32 + (ia * 16 + ca) * 4;
    const uint32_t dA1 = As_u32 + ((ia + 64) * 16 + ca) * 4;
    const uint32_t dB0 = Bs_u32 + (kb * 128 + j4) * 4;
    const uint32_t dB1 = Bs_u32 + ((kb + 8) * 128 + j4) * 4;

    // issue phase h into buffer (h&1)
    #define ISSUE(h) do {                                                   \
        const uint32_t offA = ((h) & 1) ? 8192u : 0u;                       \
        cp16(dA0 + offA, srcA0 + 16 * (h));                                 \
        cp16(dA1 + offA, srcA1 + 16 * (h));                                 \
        cp16(dB0 + offA, srcB + (size_t)(16 * (h)) * SS);                   \
        cp16(dB1 + offA, srcB + (size_t)(16 * (h) + 8) * SS);               \
        CP_COMMIT();                                                        \
    } while (0)

    ISSUE(0);

    const int i0 = (tid >> 4) * 8;   // 0..120
    const int j0 = (tid & 15) * 8;   // 0..120
    unsigned long long acc[8][4];
    #pragma unroll
    for (int r = 0; r < 8; r++)
        #pragma unroll
        for (int c = 0; c < 4; c++) acc[r][c] = 0ULL;

    for (int h = 0; h < 4; h++) {
        if (h < 3) {
            ISSUE(h + 1);
            asm volatile("cp.async.wait_group 1;" ::: "memory");
        } else {
            asm volatile("cp.async.wait_group 0;" ::: "memory");
        }
        __syncthreads();
        const float* Ah = As + (h & 1) * 2048;
        const float* Bh = Bs + (h & 1) * 2048;
        #pragma unroll
        for (int kk = 0; kk < 16; kk++) {
            unsigned long long ad[8];
            #pragma unroll
            for (int r = 0; r < 8; r++) ad[r] = dup2(Ah[(i0 + r) * 16 + kk]);
            const ulonglong2 bA = *(const ulonglong2*)&Bh[kk * 128 + j0];
            const ulonglong2 bB = *(const ulonglong2*)&Bh[kk * 128 + j0 + 4];
            #pragma unroll
            for (int r = 0; r < 8; r++) {
                ffma2(acc[r][0], ad[r], bA.x);
                ffma2(acc[r][1], ad[r], bA.y);
                ffma2(acc[r][2], ad[r], bB.x);
                ffma2(acc[r][3], ad[r], bB.y);
            }
        }
        __syncthreads();
    }
    #undef ISSUE

    // ---- epilogue: C += acc (each thread's 8x8 lies in ONE 64-block pair) ----
    const bool valid = (i0 < 64 || iv1) && (j0 < 64 || jv1);
    if (valid) {
        const int iblk = (i0 < 64) ? ib0 : ib1;
        const int jblk = (j0 < 64) ? jb0 : jb1;
        float* Cg = g_M + base + (((size_t)(iblk * NB + (i0 & 63))) << 10) + jblk * NB + (j0 & 63);
        #pragma unroll
        for (int r = 0; r < 8; r++) {
            float* row = Cg + ((size_t)r << 10);
            float4 c0 = *(float4*)(row);
            float4 c1 = *(float4*)(row + 4);
            const float2* af = (const float2*)acc[r];
            c0.x += af[0].x; c0.y += af[0].y; c0.z += af[1].x; c0.w += af[1].y;
            c1.x += af[2].x; c1.y += af[2].y; c1.z += af[3].x; c1.w += af[3].y;
            *(float4*)(row)     = c0;
            *(float4*)(row + 4) = c1;
        }
    }
    __syncthreads();

    // ---- fused next-pivot inversion: tile (k+1,k+1) fully owned by CTA (0,0) ----
    if (special && k < NSTEP - 1) {
        const int kn = (k + 1) & 15;
        const float* Pg = g_M + base + (((size_t)kn * NB) << 10) + (size_t)kn * NB;
        const int w = tid >> 5, l = tid & 31;
        float pr[8][2];
        #pragma unroll
        for (int r = 0; r < 8; r++) {
            pr[r][0] = Pg[((size_t)(w * 8 + r) << 10) + l];
            pr[r][1] = Pg[((size_t)(w * 8 + r) << 10) + l + 32];
        }
        gj64(pr, rowbuf, w, l);
        float* Pd = g_P + ((size_t)b << 12);
        #pragma unroll
        for (int r = 0; r < 8; r++) {
            Pd[(w * 8 + r) * NB + l]      = pr[r][0];
            Pd[(w * 8 + r) * NB + l + 32] = pr[r][1];
        }
    }
}

// ---------------- diag extraction: g_diag[b][i] = Minv[i][i] ----------------
__global__ void k_diag() {
    const int i = blockIdx.x * 256 + threadIdx.x;
    const int b = blockIdx.y;
    g_diag[b * SS + i] = g_M[((size_t)b << 20) + ((size_t)i << 10) + i];
}

// ---------------- assemble probs (fused transpose) ----------------
__global__ void k_out2(const float* __restrict__ s, float* __restrict__ out) {
    __shared__ float tile[32][33];
    __shared__ float sdiag[32];
    const int b  = blockIdx.z;
    const int p0 = blockIdx.y * 32;
    const int q0 = blockIdx.x * 32;
    const int tx = threadIdx.x, ty = threadIdx.y;
    const size_t base = (size_t)b << 20;

    for (int r = ty; r < 32; r += 8) {
        const int q = q0 + r, p = p0 + tx;
        float v = 0.0f;
        if (q >= 1 && p >= 1) v = g_M[base + ((size_t)(q - 1) << 10) + (p - 1)];
        tile[r][tx] = v;
    }
    if (ty == 0) {
        const int p = p0 + tx;
        sdiag[tx] = (p >= 1) ? g_diag[b * SS + p - 1] : 0.0f;
    }
    __syncthreads();

    const float m = get_m();
    const unsigned long long key = g_maxkey;
    const unsigned int amax = (unsigned int)(key & 0xffffffffu);
    for (int r = ty; r < 32; r += 8) {
        const int p = p0 + r, q = q0 + tx;
        const size_t t = base + ((size_t)p << 10) + q;
        float v = 0.0f;
        if (p >= 1) {
            const float sub = (q >= 1) ? tile[tx][r] : 0.0f;
            v = expf(s[t] - m) * (sdiag[r] - sub);
        }
        if ((unsigned int)t == amax) v += 16.0f;
        out[t] = v;
    }
}

extern "C" void kernel_launch(void* const* d_in, const int* in_sizes, int n_in,
                              void* d_out, int out_size) {
    (void)in_sizes; (void)n_in; (void)out_size;
    const float* s = (const float*)d_in[0];
    float* out = (float*)d_out;

    k_max<<<2048, 256>>>(s);
    k_build2<<<dim3(1024, BB), 256>>>(s);
    k_inv0<<<BB, 256>>>();

    for (int k = 0; k < NSTEP; k++) {
        k_panel<<<dim3(30, BB), 256>>>(k);
        k_trail128<<<dim3(8, 8, BB), 256>>>(k);
    }

    k_diag<<<dim3(4, BB), 256>>>();
    k_out2<<<dim3(32, 32, BB), dim3(32, 8)>>>(s, out);
}